// round 12
// baseline (speedup 1.0000x reference)
#include <cuda_runtime.h>
#include <cuda_fp16.h>
#include <cstdint>

// Problem constants (GCNLayer_12317966205308)
#define NN 50000
#define EE 800000
#define D  64
#define NT 256

__device__ __align__(256) float  g_acc[NN * D];   // accumulator (self-loop init, f32)
__device__ __align__(256) __half g_xwsh[NN * D];  // fp16 dis[j]*(x[j]@W) for gather
__device__ __align__(256) float  g_dis[NN];       // rsqrt(deg)
__device__ __align__(256) int    g_deg[NN];       // zero-init; reset each run in phase 2
__device__ int g_bcnt[4];                          // barrier counters (self-resetting)
__device__ int g_bsense[4];                        // barrier sense (flips each use)

// Sense-reversing grid barrier. Replay-safe: (cnt=0, sense=s) invariant after
// each use. Fence-before-arrive publishes all writes cross-block.
__device__ __forceinline__ void grid_bar(int idx) {
    __threadfence();
    __syncthreads();
    if (threadIdx.x == 0) {
        int my = atomicAdd(&g_bsense[idx], 0);
        int old = atomicAdd(&g_bcnt[idx], 1);
        if (old == (int)gridDim.x - 1) {
            g_bcnt[idx] = 0;
            __threadfence();
            atomicExch(&g_bsense[idx], 1 - my);
        } else {
            while (atomicAdd(&g_bsense[idx], 0) == my) { __nanosleep(64); }
        }
        __threadfence();
    }
    __syncthreads();
}

__device__ __forceinline__ unsigned long long pack2(float lo, float hi) {
    unsigned long long r;
    asm("mov.b64 %0, {%1, %2};" : "=l"(r) : "f"(lo), "f"(hi));
    return r;
}
__device__ __forceinline__ void unpack2(unsigned long long p, float& lo, float& hi) {
    asm("mov.b64 {%0, %1}, %2;" : "=f"(lo), "=f"(hi) : "l"(p));
}
__device__ __forceinline__ unsigned long long fma2(unsigned long long a,
                                                   unsigned long long b,
                                                   unsigned long long c) {
    unsigned long long d;
    asm("fma.rn.f32x2 %0, %1, %2, %3;" : "=l"(d) : "l"(a), "l"(b), "l"(c));
    return d;
}
__device__ __forceinline__ void red4(float* ap, float4 v) {
    asm volatile("red.global.add.v4.f32 [%0], {%1, %2, %3, %4};"
                 :: "l"(ap), "f"(v.x), "f"(v.y), "f"(v.z), "f"(v.w)
                 : "memory");
}
__device__ __forceinline__ float4 gather_h4(const __half* base, int lane) {
    uint2 raw = *reinterpret_cast<const uint2*>(base + lane * 4);
    __half2 h0 = *reinterpret_cast<__half2*>(&raw.x);
    __half2 h1 = *reinterpret_cast<__half2*>(&raw.y);
    float2 f0 = __half22float2(h0);
    float2 f1 = __half22float2(h1);
    return make_float4(f0.x, f0.y, f1.x, f1.y);
}

__global__ void __launch_bounds__(NT) k_fused(const float* __restrict__ x,
                                              const int* __restrict__ ei,
                                              const float* __restrict__ W,
                                              const float* __restrict__ b,
                                              float* __restrict__ out,
                                              int n, int E) {
    int tid = threadIdx.x;
    int gt  = blockIdx.x * NT + tid;
    int T   = gridDim.x * NT;

    // ---- Phase 1: degree histogram over dst (g_deg starts at 0) ----
    int quads = E >> 2;
    for (int q = gt; q < quads; q += T) {
        int4 d = *reinterpret_cast<const int4*>(ei + E + q * 4);
        atomicAdd(&g_deg[d.x], 1);
        atomicAdd(&g_deg[d.y], 1);
        atomicAdd(&g_deg[d.z], 1);
        atomicAdd(&g_deg[d.w], 1);
    }
    if (gt == 0)
        for (int e = quads * 4; e < E; e++) atomicAdd(&g_deg[ei[E + e]], 1);

    grid_bar(0);

    // ---- Phase 2: v = dis*(x@W); acc=v (f32); xwsh=half(v); dis; reset deg ----
    __shared__ float Ws[D * D];        // [k][c], staged ONCE per block
    __shared__ float xs[64][D + 1];    // [r][k], per tile
    {
        const float4* W4 = (const float4*)W;
        float4* Ws4 = (float4*)Ws;
        #pragma unroll
        for (int i = 0; i < 4; i++) Ws4[tid + 256 * i] = W4[tid + 256 * i];
    }
    int cg = tid & 15;   // cols [cg*4, cg*4+4)
    int rg = tid >> 4;   // rows [rg*4, rg*4+4)
    int ntiles = (n + 63) / 64;
    for (int tile = blockIdx.x; tile < ntiles; tile += gridDim.x) {
        int row0 = tile * 64;
        __syncthreads();   // previous tile's xs reads done (also orders Ws staging)
        #pragma unroll
        for (int i = 0; i < 4; i++) {
            int f = tid + 256 * i;
            int r = f >> 4, c4 = f & 15;
            int node = row0 + r;
            float4 v = (node < n) ? ((const float4*)(x + (size_t)node * D))[c4]
                                  : make_float4(0.f, 0.f, 0.f, 0.f);
            xs[r][c4 * 4 + 0] = v.x; xs[r][c4 * 4 + 1] = v.y;
            xs[r][c4 * 4 + 2] = v.z; xs[r][c4 * 4 + 3] = v.w;
        }
        __syncthreads();

        unsigned long long a01[4] = {0, 0, 0, 0};
        unsigned long long a23[4] = {0, 0, 0, 0};
        #pragma unroll 8
        for (int k = 0; k < D; k++) {
            float4 w = *(const float4*)&Ws[k * D + cg * 4];
            unsigned long long wxy = pack2(w.x, w.y);
            unsigned long long wzw = pack2(w.z, w.w);
            #pragma unroll
            for (int rr = 0; rr < 4; rr++) {
                float xv = xs[rg * 4 + rr][k];
                unsigned long long xp = pack2(xv, xv);
                a01[rr] = fma2(xp, wxy, a01[rr]);
                a23[rr] = fma2(xp, wzw, a23[rr]);
            }
        }
        #pragma unroll
        for (int rr = 0; rr < 4; rr++) {
            int node = row0 + rg * 4 + rr;
            if (node < n) {
                int degm1 = g_deg[node];
                float dis = rsqrtf((float)(degm1 + 1));   // +1 self loop
                float4 v;
                unpack2(a01[rr], v.x, v.y);
                unpack2(a23[rr], v.z, v.w);
                v.x *= dis; v.y *= dis; v.z *= dis; v.w *= dis;
                ((float4*)(g_acc + (size_t)node * D))[cg] = v;
                __half2 h0 = __floats2half2_rn(v.x, v.y);
                __half2 h1 = __floats2half2_rn(v.z, v.w);
                ((__half2*)(g_xwsh + (size_t)node * D))[cg * 2 + 0] = h0;
                ((__half2*)(g_xwsh + (size_t)node * D))[cg * 2 + 1] = h1;
                if (cg == 0) {
                    g_dis[node] = dis;
                    g_deg[node] = 0;   // reset for next replay
                }
            }
        }
    }

    grid_bar(1);

    // ---- Phase 3: edge scatter (16 threads x 4 edges/quad, fp16 gather, f32 RED) ----
    {
        int slots = quads * 16;
        for (int t = gt; t < slots; t += T) {   // T % 16 == 0 -> lane stable
            int lane = t & 15;
            int q = t >> 4;
            int e0 = q * 4;
            int4 s = *reinterpret_cast<const int4*>(ei + e0);
            int4 d = *reinterpret_cast<const int4*>(ei + E + e0);
            float4 v0 = gather_h4(g_xwsh + (size_t)s.x * D, lane);
            float4 v1 = gather_h4(g_xwsh + (size_t)s.y * D, lane);
            float4 v2 = gather_h4(g_xwsh + (size_t)s.z * D, lane);
            float4 v3 = gather_h4(g_xwsh + (size_t)s.w * D, lane);
            red4(g_acc + (size_t)d.x * D + lane * 4, v0);
            red4(g_acc + (size_t)d.y * D + lane * 4, v1);
            red4(g_acc + (size_t)d.z * D + lane * 4, v2);
            red4(g_acc + (size_t)d.w * D + lane * 4, v3);
        }
        if (gt < 16) {
            int lane = gt;
            for (int e = quads * 4; e < E; e++) {
                float4 v = gather_h4(g_xwsh + (size_t)ei[e] * D, lane);
                red4(g_acc + (size_t)ei[E + e] * D + lane * 4, v);
            }
        }
    }

    grid_bar(2);

    // ---- Phase 4: out = relu(dis*acc + b). __ldcg bypasses (possibly stale)
    // L1; streaming stores for write-once out. ----
    {
        int slots = n * 16;   // float4 slots
        for (int s = gt; s < slots; s += T) {
            float4 a = __ldcg(reinterpret_cast<const float4*>(g_acc) + s);
            float dis = g_dis[s >> 4];
            float4 bb = reinterpret_cast<const float4*>(b)[s & 15];
            float4 o;
            o.x = fmaxf(fmaf(dis, a.x, bb.x), 0.0f);
            o.y = fmaxf(fmaf(dis, a.y, bb.y), 0.0f);
            o.z = fmaxf(fmaf(dis, a.z, bb.z), 0.0f);
            o.w = fmaxf(fmaf(dis, a.w, bb.w), 0.0f);
            __stcs(reinterpret_cast<float4*>(out) + s, o);
        }
    }
}

// ---------------------------------------------------------------------------
extern "C" void kernel_launch(void* const* d_in, const int* in_sizes, int n_in,
                              void* d_out, int out_size) {
    const float* x  = (const float*)d_in[0];   // [N, 64] f32
    const int*   ei = (const int*)d_in[1];     // [2, E] int32
    const float* W  = (const float*)d_in[2];   // [64, 64] f32
    const float* b  = (const float*)d_in[3];   // [64] f32
    float* out = (float*)d_out;

    int N = in_sizes[0] / D;
    int E = in_sizes[1] / 2;

    // Max co-resident grid: occupancy query guarantees the grid barrier can't
    // deadlock, and maximizes warps/SM for the scatter phase (R11's failure
    // was 2 blocks/SM -> 24% occ). Pure host queries: capture-safe.
    int dev = 0;
    cudaGetDevice(&dev);
    int sms = 148;
    cudaDeviceGetAttribute(&sms, cudaDevAttrMultiProcessorCount, dev);
    int bpm = 2;
    cudaOccupancyMaxActiveBlocksPerMultiprocessor(&bpm, k_fused, NT, 0);
    if (bpm < 1) bpm = 1;
    int nb = sms * bpm;

    k_fused<<<nb, NT>>>(x, ei, W, b, out, N, E);
}

// round 13
// speedup vs baseline: 1.2886x; 1.2886x over previous
#include <cuda_runtime.h>
#include <cuda_fp16.h>
#include <cstdint>

// Problem constants (GCNLayer_12317966205308)
#define NN 50000
#define EE 800000
#define D  64

__device__ __align__(256) float  g_acc[NN * D];   // accumulator (init = self-loop term, f32)
__device__ __align__(256) __half g_xwsh[NN * D];  // fp16 copy of dis[j]*(x[j]@W) for gather
__device__ __align__(256) float  g_dis[NN];       // rsqrt(deg)
__device__ __align__(256) int    g_deg[NN];       // zero-init at load; k_xw resets to 0

__device__ __forceinline__ int4 ldcs4(const int* p) {
    return __ldcs(reinterpret_cast<const int4*>(p));
}

// ---------------------------------------------------------------------------
// K1: edge-count histogram over dst (g_deg starts at 0: zero-init / reset by k_xw)
__global__ void k_deg_count(const int* __restrict__ ei, int E) {
    int q = blockIdx.x * blockDim.x + threadIdx.x;
    int e0 = q * 4;
    if (e0 + 4 <= E) {
        int4 d = ldcs4(ei + E + e0);   // E % 4 == 0
        atomicAdd(&g_deg[d.x], 1);
        atomicAdd(&g_deg[d.y], 1);
        atomicAdd(&g_deg[d.z], 1);
        atomicAdd(&g_deg[d.w], 1);
    } else {
        for (int e = e0; e < E; e++) atomicAdd(&g_deg[ei[E + e]], 1);
    }
}

__device__ __forceinline__ unsigned long long pack2(float lo, float hi) {
    unsigned long long r;
    asm("mov.b64 %0, {%1, %2};" : "=l"(r) : "f"(lo), "f"(hi));
    return r;
}
__device__ __forceinline__ void unpack2(unsigned long long p, float& lo, float& hi) {
    asm("mov.b64 {%0, %1}, %2;" : "=f"(lo), "=f"(hi) : "l"(p));
}
__device__ __forceinline__ unsigned long long fma2(unsigned long long a,
                                                   unsigned long long b,
                                                   unsigned long long c) {
    unsigned long long d;
    asm("fma.rn.f32x2 %0, %1, %2, %3;" : "=l"(d) : "l"(a), "l"(b), "l"(c));
    return d;
}

// K2: v = dis * (x @ W); acc = v (f32 self-loop term); xwsh = half(v); store dis.
// deg = g_deg + 1 (self loop); resets g_deg to 0 for the next replay.
// 256 threads/block, 64 rows/block, 4x4 tile per thread, packed f32x2 FMAs.
__global__ void __launch_bounds__(256) k_xw(const float* __restrict__ x,
                                            const float* __restrict__ W, int n) {
    __shared__ float Ws[D * D];        // [k][c]
    __shared__ float xs[64][D + 1];    // [r][k], padded
    int tid = threadIdx.x;
    int row0 = blockIdx.x * 64;

    {
        const float4* W4 = (const float4*)W;
        float4* Ws4 = (float4*)Ws;
        #pragma unroll
        for (int i = 0; i < 4; i++) Ws4[tid + 256 * i] = W4[tid + 256 * i];
    }
    #pragma unroll
    for (int i = 0; i < 4; i++) {
        int f = tid + 256 * i;
        int r = f >> 4, c4 = f & 15;
        int node = row0 + r;
        float4 v = (node < n) ? ((const float4*)(x + (size_t)node * D))[c4]
                              : make_float4(0.f, 0.f, 0.f, 0.f);
        xs[r][c4 * 4 + 0] = v.x; xs[r][c4 * 4 + 1] = v.y;
        xs[r][c4 * 4 + 2] = v.z; xs[r][c4 * 4 + 3] = v.w;
    }
    __syncthreads();

    int cg = tid & 15;   // cols [cg*4, cg*4+4)
    int rg = tid >> 4;   // rows [rg*4, rg*4+4)
    unsigned long long a01[4] = {0, 0, 0, 0};   // (c0,c1) packed per row
    unsigned long long a23[4] = {0, 0, 0, 0};   // (c2,c3) packed per row
    #pragma unroll 8
    for (int k = 0; k < D; k++) {
        float4 w = *(const float4*)&Ws[k * D + cg * 4];
        unsigned long long wxy = pack2(w.x, w.y);
        unsigned long long wzw = pack2(w.z, w.w);
        #pragma unroll
        for (int rr = 0; rr < 4; rr++) {
            float xv = xs[rg * 4 + rr][k];
            unsigned long long xp = pack2(xv, xv);
            a01[rr] = fma2(xp, wxy, a01[rr]);
            a23[rr] = fma2(xp, wzw, a23[rr]);
        }
    }

    #pragma unroll
    for (int rr = 0; rr < 4; rr++) {
        int node = row0 + rg * 4 + rr;
        if (node < n) {
            int degm1 = g_deg[node];                  // broadcast load, same half-warp
            float dis = rsqrtf((float)(degm1 + 1));   // +1 = self loop
            float4 v;
            unpack2(a01[rr], v.x, v.y);
            unpack2(a23[rr], v.z, v.w);
            v.x *= dis; v.y *= dis; v.z *= dis; v.w *= dis;
            ((float4*)(g_acc + (size_t)node * D))[cg] = v;   // self-loop term
            __half2 h0 = __floats2half2_rn(v.x, v.y);
            __half2 h1 = __floats2half2_rn(v.z, v.w);
            ((__half2*)(g_xwsh + (size_t)node * D))[cg * 2 + 0] = h0;
            ((__half2*)(g_xwsh + (size_t)node * D))[cg * 2 + 1] = h1;
            if (cg == 0) {
                g_dis[node] = dis;
                g_deg[node] = 0;    // reset for next replay (after the read above)
            }
        }
    }
}

__device__ __forceinline__ void red4(float* ap, float4 v) {
    asm volatile("red.global.add.v4.f32 [%0], {%1, %2, %3, %4};"
                 :: "l"(ap), "f"(v.x), "f"(v.y), "f"(v.z), "f"(v.w)
                 : "memory");
}

__device__ __forceinline__ float4 gather_h4(const __half* base, int lane) {
    uint2 raw = *reinterpret_cast<const uint2*>(base + lane * 4);
    __half2 h0 = *reinterpret_cast<__half2*>(&raw.x);
    __half2 h1 = *reinterpret_cast<__half2*>(&raw.y);
    float2 f0 = __half22float2(h0);
    float2 f1 = __half22float2(h1);
    return make_float4(f0.x, f0.y, f1.x, f1.y);
}

// K3: edge scatter. 16 threads x 4 edges per thread-quad: streaming int4 index
// loads, 4 independent fp16 gathers (MLP=4), 4 f32 vector REDs.
__global__ void k_scatter(const int* __restrict__ ei, int E) {
    int t = blockIdx.x * blockDim.x + threadIdx.x;
    int lane = t & 15;
    int q = t >> 4;
    int e0 = q * 4;
    if (e0 >= E) return;

    if (e0 + 4 <= E) {   // fast path; E % 4 == 0
        int4 s = ldcs4(ei + e0);
        int4 d = ldcs4(ei + E + e0);
        float4 v0 = gather_h4(g_xwsh + (size_t)s.x * D, lane);
        float4 v1 = gather_h4(g_xwsh + (size_t)s.y * D, lane);
        float4 v2 = gather_h4(g_xwsh + (size_t)s.z * D, lane);
        float4 v3 = gather_h4(g_xwsh + (size_t)s.w * D, lane);
        red4(g_acc + (size_t)d.x * D + lane * 4, v0);
        red4(g_acc + (size_t)d.y * D + lane * 4, v1);
        red4(g_acc + (size_t)d.z * D + lane * 4, v2);
        red4(g_acc + (size_t)d.w * D + lane * 4, v3);
    } else {
        for (int e = e0; e < E; e++) {
            int src = ei[e], dst = ei[E + e];
            float4 v = gather_h4(g_xwsh + (size_t)src * D, lane);
            red4(g_acc + (size_t)dst * D + lane * 4, v);
        }
    }
}

// K4: out = relu(dis * acc + b), float4 vectorized
__global__ void k_final(const float* __restrict__ b, float* __restrict__ out, int n) {
    int t = blockIdx.x * blockDim.x + threadIdx.x;
    if (t >= n * (D / 4)) return;
    int node = t >> 4;
    int c4 = t & 15;
    float dis = g_dis[node];
    float4 a = reinterpret_cast<const float4*>(g_acc)[t];
    float4 bb = reinterpret_cast<const float4*>(b)[c4];
    float4 o;
    o.x = fmaxf(fmaf(dis, a.x, bb.x), 0.0f);
    o.y = fmaxf(fmaf(dis, a.y, bb.y), 0.0f);
    o.z = fmaxf(fmaf(dis, a.z, bb.z), 0.0f);
    o.w = fmaxf(fmaf(dis, a.w, bb.w), 0.0f);
    reinterpret_cast<float4*>(out)[t] = o;
}

// ---------------------------------------------------------------------------
extern "C" void kernel_launch(void* const* d_in, const int* in_sizes, int n_in,
                              void* d_out, int out_size) {
    const float* x  = (const float*)d_in[0];   // [N, 64] f32
    const int*   ei = (const int*)d_in[1];     // [2, E] int32
    const float* W  = (const float*)d_in[2];   // [64, 64] f32
    const float* b  = (const float*)d_in[3];   // [64] f32
    float* out = (float*)d_out;

    int N = in_sizes[0] / D;
    int E = in_sizes[1] / 2;
    int quads = (E + 3) / 4;

    // k_scatter uses no smem: give it the full L1 (capture-safe host attr call)
    static bool carveout_set = false;   // idempotent config, not a work guard
    if (!carveout_set) {
        cudaFuncSetAttribute(k_scatter, cudaFuncAttributePreferredSharedMemoryCarveout, 0);
        carveout_set = true;
    }

    k_deg_count<<<(quads + 255) / 256, 256>>>(ei, E);
    k_xw<<<(N + 63) / 64, 256>>>(x, W, N);
    {
        long long work = (long long)quads * 16;
        k_scatter<<<(int)((work + 255) / 256), 256>>>(ei, E);
    }
    {
        int work = N * (D / 4);
        k_final<<<(work + 255) / 256, 256>>>(b, out, N);
    }
}

// round 15
// speedup vs baseline: 1.3313x; 1.0331x over previous
#include <cuda_runtime.h>
#include <cuda_fp16.h>
#include <cstdint>

// Problem constants (GCNLayer_12317966205308)
#define NN 50000
#define EE 800000
#define D  64

__device__ __align__(256) float  g_acc[NN * D];   // accumulator (init = self-loop term, f32)
__device__ __align__(256) __half g_xwsh[NN * D];  // fp16 copy of dis[j]*(x[j]@W) for gather
__device__ __align__(256) float  g_dis[NN];       // rsqrt(deg)
__device__ __align__(256) int    g_deg[NN];       // zero-init at load; k_xw resets to 0

__device__ __forceinline__ int4 ldcs4(const int* p) {
    return __ldcs(reinterpret_cast<const int4*>(p));
}

// ---------------------------------------------------------------------------
// K1: edge-count histogram over dst (g_deg starts at 0: zero-init / reset by k_xw)
__global__ void k_deg_count(const int* __restrict__ ei, int E) {
    int q = blockIdx.x * blockDim.x + threadIdx.x;
    int e0 = q * 4;
    if (e0 + 4 <= E) {
        int4 d = ldcs4(ei + E + e0);   // E % 4 == 0
        atomicAdd(&g_deg[d.x], 1);
        atomicAdd(&g_deg[d.y], 1);
        atomicAdd(&g_deg[d.z], 1);
        atomicAdd(&g_deg[d.w], 1);
    } else {
        for (int e = e0; e < E; e++) atomicAdd(&g_deg[ei[E + e]], 1);
    }
}

__device__ __forceinline__ unsigned long long pack2(float lo, float hi) {
    unsigned long long r;
    asm("mov.b64 %0, {%1, %2};" : "=l"(r) : "f"(lo), "f"(hi));
    return r;
}
__device__ __forceinline__ void unpack2(unsigned long long p, float& lo, float& hi) {
    asm("mov.b64 {%0, %1}, %2;" : "=f"(lo), "=f"(hi) : "l"(p));
}
__device__ __forceinline__ unsigned long long fma2(unsigned long long a,
                                                   unsigned long long b,
                                                   unsigned long long c) {
    unsigned long long d;
    asm("fma.rn.f32x2 %0, %1, %2, %3;" : "=l"(d) : "l"(a), "l"(b), "l"(c));
    return d;
}

// K2: v = dis * (x @ W); acc = v (f32 self-loop term); xwsh = half(v); store dis.
// PDL: the whole GEMM (x, W = kernel inputs) runs BEFORE the dependency sync;
// only the deg read + stores wait for k_deg_count. deg = g_deg + 1 (self loop);
// resets g_deg to 0 for the next replay.
__global__ void __launch_bounds__(256) k_xw(const float* __restrict__ x,
                                            const float* __restrict__ W, int n) {
    __shared__ float Ws[D * D];        // [k][c]
    __shared__ float xs[64][D + 1];    // [r][k], padded
    int tid = threadIdx.x;
    int row0 = blockIdx.x * 64;

    {
        const float4* W4 = (const float4*)W;
        float4* Ws4 = (float4*)Ws;
        #pragma unroll
        for (int i = 0; i < 4; i++) Ws4[tid + 256 * i] = W4[tid + 256 * i];
    }
    #pragma unroll
    for (int i = 0; i < 4; i++) {
        int f = tid + 256 * i;
        int r = f >> 4, c4 = f & 15;
        int node = row0 + r;
        float4 v = (node < n) ? ((const float4*)(x + (size_t)node * D))[c4]
                              : make_float4(0.f, 0.f, 0.f, 0.f);
        xs[r][c4 * 4 + 0] = v.x; xs[r][c4 * 4 + 1] = v.y;
        xs[r][c4 * 4 + 2] = v.z; xs[r][c4 * 4 + 3] = v.w;
    }
    __syncthreads();

    int cg = tid & 15;   // cols [cg*4, cg*4+4)
    int rg = tid >> 4;   // rows [rg*4, rg*4+4)
    unsigned long long a01[4] = {0, 0, 0, 0};   // (c0,c1) packed per row
    unsigned long long a23[4] = {0, 0, 0, 0};   // (c2,c3) packed per row
    #pragma unroll 8
    for (int k = 0; k < D; k++) {
        float4 w = *(const float4*)&Ws[k * D + cg * 4];
        unsigned long long wxy = pack2(w.x, w.y);
        unsigned long long wzw = pack2(w.z, w.w);
        #pragma unroll
        for (int rr = 0; rr < 4; rr++) {
            float xv = xs[rg * 4 + rr][k];
            unsigned long long xp = pack2(xv, xv);
            a01[rr] = fma2(xp, wxy, a01[rr]);
            a23[rr] = fma2(xp, wzw, a23[rr]);
        }
    }

    // Wait for k_deg_count's writes to be complete+visible, then finish.
    cudaGridDependencySynchronize();

    #pragma unroll
    for (int rr = 0; rr < 4; rr++) {
        int node = row0 + rg * 4 + rr;
        if (node < n) {
            int degm1 = g_deg[node];                  // broadcast load, same half-warp
            float dis = rsqrtf((float)(degm1 + 1));   // +1 = self loop
            float4 v;
            unpack2(a01[rr], v.x, v.y);
            unpack2(a23[rr], v.z, v.w);
            v.x *= dis; v.y *= dis; v.z *= dis; v.w *= dis;
            ((float4*)(g_acc + (size_t)node * D))[cg] = v;   // self-loop term
            __half2 h0 = __floats2half2_rn(v.x, v.y);
            __half2 h1 = __floats2half2_rn(v.z, v.w);
            ((__half2*)(g_xwsh + (size_t)node * D))[cg * 2 + 0] = h0;
            ((__half2*)(g_xwsh + (size_t)node * D))[cg * 2 + 1] = h1;
            if (cg == 0) {
                g_dis[node] = dis;
                g_deg[node] = 0;    // reset for next replay (after the read above)
            }
        }
    }
}

__device__ __forceinline__ void red4(float* ap, float4 v) {
    asm volatile("red.global.add.v4.f32 [%0], {%1, %2, %3, %4};"
                 :: "l"(ap), "f"(v.x), "f"(v.y), "f"(v.z), "f"(v.w)
                 : "memory");
}

__device__ __forceinline__ float4 gather_h4(const __half* base, int lane) {
    uint2 raw = *reinterpret_cast<const uint2*>(base + lane * 4);
    __half2 h0 = *reinterpret_cast<__half2*>(&raw.x);
    __half2 h1 = *reinterpret_cast<__half2*>(&raw.y);
    float2 f0 = __half22float2(h0);
    float2 f1 = __half22float2(h1);
    return make_float4(f0.x, f0.y, f1.x, f1.y);
}

// K3: edge scatter. 16 threads x 4 edges per quad. PDL: index loads (input ei)
// issue pre-sync; gathers/REDs wait for k_xw.
__global__ void k_scatter(const int* __restrict__ ei, int E) {
    int t = blockIdx.x * blockDim.x + threadIdx.x;
    int lane = t & 15;
    int q = t >> 4;
    int e0 = q * 4;

    if (e0 + 4 <= E) {   // fast path; E % 4 == 0
        int4 s = ldcs4(ei + e0);
        int4 d = ldcs4(ei + E + e0);
        cudaGridDependencySynchronize();
        float4 v0 = gather_h4(g_xwsh + (size_t)s.x * D, lane);
        float4 v1 = gather_h4(g_xwsh + (size_t)s.y * D, lane);
        float4 v2 = gather_h4(g_xwsh + (size_t)s.z * D, lane);
        float4 v3 = gather_h4(g_xwsh + (size_t)s.w * D, lane);
        red4(g_acc + (size_t)d.x * D + lane * 4, v0);
        red4(g_acc + (size_t)d.y * D + lane * 4, v1);
        red4(g_acc + (size_t)d.z * D + lane * 4, v2);
        red4(g_acc + (size_t)d.w * D + lane * 4, v3);
    } else {
        cudaGridDependencySynchronize();
        for (int e = e0; e < E; e++) {
            int src = ei[e], dst = ei[E + e];
            float4 v = gather_h4(g_xwsh + (size_t)src * D, lane);
            red4(g_acc + (size_t)dst * D + lane * 4, v);
        }
    }
}

// K4: out = relu(dis * acc + b). PDL: sync at entry (everything depends on scatter).
__global__ void k_final(const float* __restrict__ b, float* __restrict__ out, int n) {
    cudaGridDependencySynchronize();
    int t = blockIdx.x * blockDim.x + threadIdx.x;
    if (t >= n * (D / 4)) return;
    int node = t >> 4;
    int c4 = t & 15;
    float dis = g_dis[node];
    float4 a = reinterpret_cast<const float4*>(g_acc)[t];
    float4 bb = reinterpret_cast<const float4*>(b)[c4];
    float4 o;
    o.x = fmaxf(fmaf(dis, a.x, bb.x), 0.0f);
    o.y = fmaxf(fmaf(dis, a.y, bb.y), 0.0f);
    o.z = fmaxf(fmaf(dis, a.z, bb.z), 0.0f);
    o.w = fmaxf(fmaf(dis, a.w, bb.w), 0.0f);
    reinterpret_cast<float4*>(out)[t] = o;
}

// ---------------------------------------------------------------------------
static void launch_pdl(void* fn, dim3 grid, dim3 block,
                       void** args) {
    cudaLaunchConfig_t cfg = {};
    cfg.gridDim = grid;
    cfg.blockDim = block;
    cfg.dynamicSmemBytes = 0;
    cfg.stream = 0;
    cudaLaunchAttribute attr[1];
    attr[0].id = cudaLaunchAttributeProgrammaticStreamSerialization;
    attr[0].val.programmaticStreamSerializationAllowed = 1;   // CUDA 13 member name
    cfg.attrs = attr;
    cfg.numAttrs = 1;
    cudaLaunchKernelExC(&cfg, fn, args);
}

extern "C" void kernel_launch(void* const* d_in, const int* in_sizes, int n_in,
                              void* d_out, int out_size) {
    const float* x  = (const float*)d_in[0];   // [N, 64] f32
    const int*   ei = (const int*)d_in[1];     // [2, E] int32
    const float* W  = (const float*)d_in[2];   // [64, 64] f32
    const float* b  = (const float*)d_in[3];   // [64] f32
    float* out = (float*)d_out;

    int N = in_sizes[0] / D;
    int E = in_sizes[1] / 2;
    int quads = (E + 3) / 4;

    // K1: normal launch
    k_deg_count<<<(quads + 255) / 256, 256>>>(ei, E);

    // K2..K4: programmatic dependent launches (prologue overlaps predecessor drain)
    {
        void* args[] = { (void*)&x, (void*)&W, (void*)&N };
        launch_pdl((void*)k_xw, dim3((N + 63) / 64), dim3(256), args);
    }
    {
        long long work = (long long)quads * 16;
        int grid = (int)((work + 255) / 256);
        void* args[] = { (void*)&ei, (void*)&E };
        launch_pdl((void*)k_scatter, dim3(grid), dim3(256), args);
    }
    {
        int work = N * (D / 4);
        int grid = (work + 255) / 256;
        void* args[] = { (void*)&b, (void*)&out, (void*)&N };
        launch_pdl((void*)k_final, dim3(grid), dim3(256), args);
    }
}